// round 7
// baseline (speedup 1.0000x reference)
#include <cuda_runtime.h>
#include <math.h>

#define SS 4096
#define VV 2048
#define BB 8
#define LL 32
#define WW 8
#define ZP 16

// Scratch (no allocation allowed in kernel_launch)
__device__ float g_lse[SS];
__device__ float g_prior[SS];
__device__ float g_logp[SS * 7];
__device__ float g_smt[(size_t)VV * SS];   // transposed smoothed emissions: [v][s]
__device__ float g_emis[LL * BB * SS];     // all_emis, layout (l, b, s)

// Order-preserving float <-> uint key (for REDUX.UMAX warp reduction)
__device__ __forceinline__ unsigned f2key(float f) {
    unsigned u = __float_as_uint(f);
    return u ^ (unsigned)(((int)u >> 31) | 0x80000000);
}
__device__ __forceinline__ float key2f(unsigned k) {
    unsigned u = (k & 0x80000000u) ? (k ^ 0x80000000u) : ~k;
    return __uint_as_float(u);
}

// ---------------------------------------------------------------------------
// K1: per-row logsumexp of emis_w (one warp per row, float4 vectorized)
// ---------------------------------------------------------------------------
__global__ void k_row_lse(const float* __restrict__ w) {
    int row  = blockIdx.x * 8 + (threadIdx.x >> 5);
    int lane = threadIdx.x & 31;
    const float4* r = (const float4*)(w + (size_t)row * VV);
    float m = -1e30f;
#pragma unroll
    for (int i = 0; i < 16; i++) {
        float4 v = r[lane + 32 * i];
        m = fmaxf(m, fmaxf(fmaxf(v.x, v.y), fmaxf(v.z, v.w)));
    }
#pragma unroll
    for (int o = 16; o; o >>= 1) m = fmaxf(m, __shfl_xor_sync(0xffffffffu, m, o));
    float s = 0.f;
#pragma unroll
    for (int i = 0; i < 16; i++) {
        float4 v = r[lane + 32 * i];
        s += __expf(v.x - m) + __expf(v.y - m) + __expf(v.z - m) + __expf(v.w - m);
    }
#pragma unroll
    for (int o = 16; o; o >>= 1) s += __shfl_xor_sync(0xffffffffu, s, o);
    if (lane == 0) g_lse[row] = m + __logf(s);
}

// ---------------------------------------------------------------------------
// K1bc fused: block 0 = prior log_softmax; blocks 1..4 = transition logp
// ---------------------------------------------------------------------------
__global__ __launch_bounds__(1024) void k_small(const float* __restrict__ pw,
                                                const float* __restrict__ tw) {
    if (blockIdx.x == 0) {
        __shared__ float red[32];
        __shared__ float bval;
        int tid = threadIdx.x;
        float v[4];
#pragma unroll
        for (int i = 0; i < 4; i++) v[i] = pw[tid + i * 1024];
        float m = fmaxf(fmaxf(v[0], v[1]), fmaxf(v[2], v[3]));
#pragma unroll
        for (int o = 16; o; o >>= 1) m = fmaxf(m, __shfl_xor_sync(0xffffffffu, m, o));
        if ((tid & 31) == 0) red[tid >> 5] = m;
        __syncthreads();
        if (tid < 32) {
            float t = red[tid];
#pragma unroll
            for (int o = 16; o; o >>= 1) t = fmaxf(t, __shfl_xor_sync(0xffffffffu, t, o));
            if (tid == 0) bval = t;
        }
        __syncthreads();
        m = bval;
        float s = __expf(v[0] - m) + __expf(v[1] - m) + __expf(v[2] - m) + __expf(v[3] - m);
#pragma unroll
        for (int o = 16; o; o >>= 1) s += __shfl_xor_sync(0xffffffffu, s, o);
        if ((tid & 31) == 0) red[tid >> 5] = s;
        __syncthreads();
        if (tid < 32) {
            float t = red[tid];
#pragma unroll
            for (int o = 16; o; o >>= 1) t += __shfl_xor_sync(0xffffffffu, t, o);
            if (tid == 0) bval = t;
        }
        __syncthreads();
        float lse = m + __logf(bval);
#pragma unroll
        for (int i = 0; i < 4; i++) g_prior[tid + i * 1024] = v[i] - lse;
    } else {
        int j = (blockIdx.x - 1) * 1024 + threadIdx.x;
        int x = j & 15, y = (j >> 4) & 15, z = j >> 8;
        int v1 = (x < 15), v2 = (x > 0), v3 = (y < 15), v4 = (y > 0), v5 = (z < 15), v6 = (z < 14);
        int nv = 1 + v1 + v2 + v3 + v4 + v5 + v6;
        float w[7];
#pragma unroll
        for (int k = 0; k < 7; k++) w[k] = tw[j * 7 + k];
        float m = w[0];
#pragma unroll
        for (int k = 1; k < 7; k++) if (k < nv) m = fmaxf(m, w[k]);
        float s = 0.f;
#pragma unroll
        for (int k = 0; k < 7; k++) if (k < nv) s += __expf(w[k] - m);
        float lse = m + __logf(s);
        int p2 = 1 + v1;
        int p3 = p2 + v2;
        int p4 = p3 + v3;
        int p5 = p4 + v4;
        int p6 = p5 + v5;
        float* o = g_logp + j * 7;
        o[0] = w[0] - lse;
        o[1] = v1 ? w[1]  - lse : -1e30f;
        o[2] = v2 ? w[p2] - lse : -1e30f;
        o[3] = v3 ? w[p3] - lse : -1e30f;
        o[4] = v4 ? w[p4] - lse : -1e30f;
        o[5] = v5 ? w[p5] - lse : -1e30f;
        o[6] = v6 ? w[p6] - lse : -1e30f;
    }
}

// ---------------------------------------------------------------------------
// K2: smoothed emissions, stored TRANSPOSED (SMT[v][s]).
// One block = one z-plane (256 states) x 64 vocab columns, 512 threads.
// Dynamic smem: P[256][67] (pad 67 -> phase-2 reads stride 3 mod 32 =
// bank permutation, conflict-free).
// ---------------------------------------------------------------------------
__global__ __launch_bounds__(512) void k_smt(const float* __restrict__ ew) {
    extern __shared__ float P[];          // 256*67 floats = 68608 B
    __shared__ float slse[256];
    int tx = threadIdx.x & 31;
    int ty = threadIdx.x >> 5;            // 0..15
    int v0 = blockIdx.x * 64;
    int sbase = blockIdx.y * 256;         // z-plane

    if (threadIdx.x < 256) slse[threadIdx.x] = g_lse[sbase + threadIdx.x];
    __syncthreads();

#pragma unroll
    for (int i = 0; i < 16; i++) {
        int sl = ty + 16 * i;
        float l = slse[sl];
        const float* row = ew + (size_t)(sbase + sl) * VV + v0;
        P[sl * 67 + tx]      = __expf(row[tx]      - l);
        P[sl * 67 + 32 + tx] = __expf(row[32 + tx] - l);
    }
    __syncthreads();

#pragma unroll
    for (int jb = 0; jb < 8; jb++) {
        int sl = jb * 32 + tx;
        int x = sl & 15, y = sl >> 4;
        int sxp = sl + (x < 15);
        int sxm = sl - (x > 0);
        int syp = sl + ((y < 15) ? 16 : 0);
        int sym = sl - ((y > 0)  ? 16 : 0);
#pragma unroll
        for (int k = 0; k < 4; k++) {
            int vl = ty + 16 * k;          // 0..63
            float q = P[sl * 67 + vl] + P[sxp * 67 + vl] + P[sxm * 67 + vl]
                    + P[syp * 67 + vl] + P[sym * 67 + vl];
            g_smt[(size_t)(v0 + vl) * SS + sbase + sl] = __logf(q * 0.2f);
        }
    }
}

// ---------------------------------------------------------------------------
// K3: all_emis[l,b,s] = sum_w SMT[tok][s]  (tok == V contributes 0)
// ---------------------------------------------------------------------------
__global__ void k_emis(const int* __restrict__ stories) {
    int s  = blockIdx.x * 256 + threadIdx.x;
    int lb = blockIdx.y;           // lb = l*8 + b
    int l = lb >> 3, b = lb & 7;
    const int* tk = stories + (b * LL + l) * WW;
    float acc = 0.f;
#pragma unroll
    for (int w = 0; w < WW; w++) {
        int t = __ldg(&tk[w]);
        if (t < VV) acc += g_smt[(size_t)t * SS + s];
    }
    g_emis[(size_t)lb * SS + s] = acc;
}

// ---------------------------------------------------------------------------
// K4: forward recurrence in probability space. One CTA per batch; 4 states
// per thread; scores in registers, p staged in smem. Block max via
// REDUX (single-instruction warp max on order-preserving uint keys).
// Next step's emission prefetched before the barrier; am[] folded into it.
// ---------------------------------------------------------------------------
__global__ __launch_bounds__(1024, 1) void k_fwd(float* __restrict__ out) {
    __shared__ float pbuf[SS];
    __shared__ unsigned wkey[32];
    int b   = blockIdx.x;
    int tid = threadIdx.x;
    int wid = tid >> 5, lane = tid & 31;
    int j0 = tid * 4;
    int x0 = j0 & 15;          // 0,4,8,12
    int y  = (j0 >> 4) & 15;
    int z  = j0 >> 8;

    // Per-state amax + renormalized transition probs (once).
    float Pk[4][7], am[4];
#pragma unroll
    for (int e = 0; e < 4; e++) {
        const float* lp = g_logp + (j0 + e) * 7;
        float l[7];
#pragma unroll
        for (int k = 0; k < 7; k++) l[k] = lp[k];
        float m = l[0];
#pragma unroll
        for (int k = 1; k < 7; k++) m = fmaxf(m, l[k]);
        am[e] = m;
#pragma unroll
        for (int k = 0; k < 7; k++) Pk[e][k] = __expf(l[k] - m);  // invalid -> 0
    }

    // l = 0: score0 = emis[0,b,:] + prior
    float4 emv = *(const float4*)(g_emis + (size_t)b * SS + j0);
    float4 prv = *(const float4*)(g_prior + j0);
    float sc[4];
    sc[0] = emv.x + prv.x; sc[1] = emv.y + prv.y;
    sc[2] = emv.z + prv.z; sc[3] = emv.w + prv.w;
    *(float4*)(out + (size_t)b * SS + j0) = make_float4(sc[0], sc[1], sc[2], sc[3]);

    // block max of scores (REDUX two-level)
    float lm = fmaxf(fmaxf(sc[0], sc[1]), fmaxf(sc[2], sc[3]));
    unsigned km = __reduce_max_sync(0xffffffffu, f2key(lm));
    if (lane == 0) wkey[wid] = km;

    // prefetch emission for l = 1
    float4 emn = *(const float4*)(g_emis + (size_t)(BB + b) * SS + j0);

    __syncthreads();
    float smax = key2f(__reduce_max_sync(0xffffffffu, wkey[lane]));

    for (int l = 1; l < LL; l++) {
        // stage p = exp(score - smax)
        float4 p;
        p.x = __expf(sc[0] - smax); p.y = __expf(sc[1] - smax);
        p.z = __expf(sc[2] - smax); p.w = __expf(sc[3] - smax);
        *(float4*)(pbuf + j0) = p;

        // emission + amax add-back (off the critical path)
        float emr[4] = {emn.x + am[0], emn.y + am[1], emn.z + am[2], emn.w + am[3]};
        // prefetch next step's emission
        if (l + 1 < LL)
            emn = *(const float4*)(g_emis + (size_t)((l + 1) * BB + b) * SS + j0);

        __syncthreads();   // [A] pbuf published

        // gathers (clamped neighbors fall back to self; Pk==0 kills invalid)
        float cm1 = (x0 > 0)  ? pbuf[j0 - 1] : p.x;
        float cp4 = (x0 < 12) ? pbuf[j0 + 4] : p.w;
        float4 yp = (y < 15) ? *(const float4*)(pbuf + j0 + 16)  : p;
        float4 ym = (y > 0)  ? *(const float4*)(pbuf + j0 - 16)  : p;
        float4 zp = (z < 15) ? *(const float4*)(pbuf + j0 + 256) : p;
        float4 zq = (z < 14) ? *(const float4*)(pbuf + j0 + 512) : p;

        float pc[4]  = {p.x, p.y, p.z, p.w};
        float pxp[4] = {p.y, p.z, p.w, cp4};
        float pxm[4] = {cm1, p.x, p.y, p.z};
        float pyp[4] = {yp.x, yp.y, yp.z, yp.w};
        float pym[4] = {ym.x, ym.y, ym.z, ym.w};
        float pzp[4] = {zp.x, zp.y, zp.z, zp.w};
        float pzq[4] = {zq.x, zq.y, zq.z, zq.w};

        float lmn = -1e30f;
#pragma unroll
        for (int e = 0; e < 4; e++) {
            float q = pc[e]  * Pk[e][0];
            q = fmaf(pxp[e], Pk[e][1], q);
            q = fmaf(pxm[e], Pk[e][2], q);
            q = fmaf(pyp[e], Pk[e][3], q);
            q = fmaf(pym[e], Pk[e][4], q);
            q = fmaf(pzp[e], Pk[e][5], q);
            q = fmaf(pzq[e], Pk[e][6], q);
            sc[e] = emr[e] + __logf(q) + smax;
            lmn = fmaxf(lmn, sc[e]);
        }
        *(float4*)(out + (size_t)(l * BB + b) * SS + j0) =
            make_float4(sc[0], sc[1], sc[2], sc[3]);

        // block max for next step's normalizer
        km = __reduce_max_sync(0xffffffffu, f2key(lmn));
        if (lane == 0) wkey[wid] = km;
        __syncthreads();   // [B] wkey published; also guards pbuf WAR
        smax = key2f(__reduce_max_sync(0xffffffffu, wkey[lane]));
    }
}

// ---------------------------------------------------------------------------
extern "C" void kernel_launch(void* const* d_in, const int* in_sizes, int n_in,
                              void* d_out, int out_size) {
    const int*   stories = nullptr;
    const float* trans_w = nullptr;
    const float* emis_w  = nullptr;
    const float* prior_w = nullptr;
    for (int i = 0; i < n_in; i++) {
        switch (in_sizes[i]) {
            case 2048:            stories = (const int*)d_in[i];   break;
            case 28672:           trans_w = (const float*)d_in[i]; break;
            case SS * VV:         emis_w  = (const float*)d_in[i]; break;
            case SS:              prior_w = (const float*)d_in[i]; break;
            default: break;
        }
    }
    float* out = (float*)d_out;

    const int smt_smem = 256 * 67 * sizeof(float);   // 68608 B
    cudaFuncSetAttribute(k_smt, cudaFuncAttributeMaxDynamicSharedMemorySize, smt_smem);

    k_row_lse<<<512, 256>>>(emis_w);
    k_small<<<5, 1024>>>(prior_w, trans_w);
    k_smt<<<dim3(VV / 64, ZP), 512, smt_smem>>>(emis_w);
    k_emis<<<dim3(SS / 256, LL * BB), 256>>>(stories);
    k_fwd<<<BB, 1024>>>(out);
    (void)out_size;
}

// round 8
// speedup vs baseline: 1.0036x; 1.0036x over previous
#include <cuda_runtime.h>
#include <math.h>

#define SS 4096
#define VV 2048
#define BB 8
#define LL 32
#define WW 8
#define ZP 16

// Scratch (no allocation allowed in kernel_launch)
__device__ float g_lse[SS];
__device__ float g_prior[SS];
__device__ float g_logp[SS * 7];
__device__ float g_smt[(size_t)VV * SS];   // transposed smoothed emissions: [v][s]
__device__ float g_emis[LL * BB * SS];     // all_emis, layout (l, b, s)

// Order-preserving float <-> uint key (for REDUX.UMAX warp reduction)
__device__ __forceinline__ unsigned f2key(float f) {
    unsigned u = __float_as_uint(f);
    return u ^ (unsigned)(((int)u >> 31) | 0x80000000);
}
__device__ __forceinline__ float key2f(unsigned k) {
    unsigned u = (k & 0x80000000u) ? (k ^ 0x80000000u) : ~k;
    return __uint_as_float(u);
}

// ---------------------------------------------------------------------------
// K1: per-row logsumexp of emis_w (one warp per row, float4 vectorized)
// ---------------------------------------------------------------------------
__global__ void k_row_lse(const float* __restrict__ w) {
    int row  = blockIdx.x * 8 + (threadIdx.x >> 5);
    int lane = threadIdx.x & 31;
    const float4* r = (const float4*)(w + (size_t)row * VV);
    float m = -1e30f;
#pragma unroll
    for (int i = 0; i < 16; i++) {
        float4 v = r[lane + 32 * i];
        m = fmaxf(m, fmaxf(fmaxf(v.x, v.y), fmaxf(v.z, v.w)));
    }
#pragma unroll
    for (int o = 16; o; o >>= 1) m = fmaxf(m, __shfl_xor_sync(0xffffffffu, m, o));
    float s = 0.f;
#pragma unroll
    for (int i = 0; i < 16; i++) {
        float4 v = r[lane + 32 * i];
        s += __expf(v.x - m) + __expf(v.y - m) + __expf(v.z - m) + __expf(v.w - m);
    }
#pragma unroll
    for (int o = 16; o; o >>= 1) s += __shfl_xor_sync(0xffffffffu, s, o);
    if (lane == 0) g_lse[row] = m + __logf(s);
}

// ---------------------------------------------------------------------------
// K1bc fused: block 0 = prior log_softmax; blocks 1..4 = transition logp
// ---------------------------------------------------------------------------
__global__ __launch_bounds__(1024) void k_small(const float* __restrict__ pw,
                                                const float* __restrict__ tw) {
    if (blockIdx.x == 0) {
        __shared__ float red[32];
        __shared__ float bval;
        int tid = threadIdx.x;
        float v[4];
#pragma unroll
        for (int i = 0; i < 4; i++) v[i] = pw[tid + i * 1024];
        float m = fmaxf(fmaxf(v[0], v[1]), fmaxf(v[2], v[3]));
#pragma unroll
        for (int o = 16; o; o >>= 1) m = fmaxf(m, __shfl_xor_sync(0xffffffffu, m, o));
        if ((tid & 31) == 0) red[tid >> 5] = m;
        __syncthreads();
        if (tid < 32) {
            float t = red[tid];
#pragma unroll
            for (int o = 16; o; o >>= 1) t = fmaxf(t, __shfl_xor_sync(0xffffffffu, t, o));
            if (tid == 0) bval = t;
        }
        __syncthreads();
        m = bval;
        float s = __expf(v[0] - m) + __expf(v[1] - m) + __expf(v[2] - m) + __expf(v[3] - m);
#pragma unroll
        for (int o = 16; o; o >>= 1) s += __shfl_xor_sync(0xffffffffu, s, o);
        if ((tid & 31) == 0) red[tid >> 5] = s;
        __syncthreads();
        if (tid < 32) {
            float t = red[tid];
#pragma unroll
            for (int o = 16; o; o >>= 1) t += __shfl_xor_sync(0xffffffffu, t, o);
            if (tid == 0) bval = t;
        }
        __syncthreads();
        float lse = m + __logf(bval);
#pragma unroll
        for (int i = 0; i < 4; i++) g_prior[tid + i * 1024] = v[i] - lse;
    } else {
        int j = (blockIdx.x - 1) * 1024 + threadIdx.x;
        int x = j & 15, y = (j >> 4) & 15, z = j >> 8;
        int v1 = (x < 15), v2 = (x > 0), v3 = (y < 15), v4 = (y > 0), v5 = (z < 15), v6 = (z < 14);
        int nv = 1 + v1 + v2 + v3 + v4 + v5 + v6;
        float w[7];
#pragma unroll
        for (int k = 0; k < 7; k++) w[k] = tw[j * 7 + k];
        float m = w[0];
#pragma unroll
        for (int k = 1; k < 7; k++) if (k < nv) m = fmaxf(m, w[k]);
        float s = 0.f;
#pragma unroll
        for (int k = 0; k < 7; k++) if (k < nv) s += __expf(w[k] - m);
        float lse = m + __logf(s);
        int p2 = 1 + v1;
        int p3 = p2 + v2;
        int p4 = p3 + v3;
        int p5 = p4 + v4;
        int p6 = p5 + v5;
        float* o = g_logp + j * 7;
        o[0] = w[0] - lse;
        o[1] = v1 ? w[1]  - lse : -1e30f;
        o[2] = v2 ? w[p2] - lse : -1e30f;
        o[3] = v3 ? w[p3] - lse : -1e30f;
        o[4] = v4 ? w[p4] - lse : -1e30f;
        o[5] = v5 ? w[p5] - lse : -1e30f;
        o[6] = v6 ? w[p6] - lse : -1e30f;
    }
}

// ---------------------------------------------------------------------------
// K2: smoothed emissions, stored TRANSPOSED (SMT[v][s]).
// One block = one z-plane (256 states) x 64 vocab columns, 512 threads.
// Dynamic smem: P[256][67] (pad 67 -> phase-2 reads stride 3 mod 32 =
// bank permutation, conflict-free).
// ---------------------------------------------------------------------------
__global__ __launch_bounds__(512) void k_smt(const float* __restrict__ ew) {
    extern __shared__ float P[];          // 256*67 floats = 68608 B
    __shared__ float slse[256];
    int tx = threadIdx.x & 31;
    int ty = threadIdx.x >> 5;            // 0..15
    int v0 = blockIdx.x * 64;
    int sbase = blockIdx.y * 256;         // z-plane

    if (threadIdx.x < 256) slse[threadIdx.x] = g_lse[sbase + threadIdx.x];
    __syncthreads();

#pragma unroll
    for (int i = 0; i < 16; i++) {
        int sl = ty + 16 * i;
        float l = slse[sl];
        const float* row = ew + (size_t)(sbase + sl) * VV + v0;
        P[sl * 67 + tx]      = __expf(row[tx]      - l);
        P[sl * 67 + 32 + tx] = __expf(row[32 + tx] - l);
    }
    __syncthreads();

#pragma unroll
    for (int jb = 0; jb < 8; jb++) {
        int sl = jb * 32 + tx;
        int x = sl & 15, y = sl >> 4;
        int sxp = sl + (x < 15);
        int sxm = sl - (x > 0);
        int syp = sl + ((y < 15) ? 16 : 0);
        int sym = sl - ((y > 0)  ? 16 : 0);
#pragma unroll
        for (int k = 0; k < 4; k++) {
            int vl = ty + 16 * k;          // 0..63
            float q = P[sl * 67 + vl] + P[sxp * 67 + vl] + P[sxm * 67 + vl]
                    + P[syp * 67 + vl] + P[sym * 67 + vl];
            g_smt[(size_t)(v0 + vl) * SS + sbase + sl] = __logf(q * 0.2f);
        }
    }
}

// ---------------------------------------------------------------------------
// K3: all_emis[l,b,s] = sum_w SMT[tok][s]  (tok == V contributes 0)
// ---------------------------------------------------------------------------
__global__ void k_emis(const int* __restrict__ stories) {
    int s  = blockIdx.x * 256 + threadIdx.x;
    int lb = blockIdx.y;           // lb = l*8 + b
    int l = lb >> 3, b = lb & 7;
    const int* tk = stories + (b * LL + l) * WW;
    float acc = 0.f;
#pragma unroll
    for (int w = 0; w < WW; w++) {
        int t = __ldg(&tk[w]);
        if (t < VV) acc += g_smt[(size_t)t * SS + s];
    }
    g_emis[(size_t)lb * SS + s] = acc;
}

// ---------------------------------------------------------------------------
// K4: forward recurrence in probability space. One CTA per batch; 4 states
// per thread; scores in registers, p staged in smem. Block max via
// REDUX (single-instruction warp max on order-preserving uint keys).
// Next step's emission prefetched before the barrier; am[] folded into it.
// ---------------------------------------------------------------------------
__global__ __launch_bounds__(1024, 1) void k_fwd(float* __restrict__ out) {
    __shared__ float pbuf[SS];
    __shared__ unsigned wkey[32];
    int b   = blockIdx.x;
    int tid = threadIdx.x;
    int wid = tid >> 5, lane = tid & 31;
    int j0 = tid * 4;
    int x0 = j0 & 15;          // 0,4,8,12
    int y  = (j0 >> 4) & 15;
    int z  = j0 >> 8;

    // Per-state amax + renormalized transition probs (once).
    float Pk[4][7], am[4];
#pragma unroll
    for (int e = 0; e < 4; e++) {
        const float* lp = g_logp + (j0 + e) * 7;
        float l[7];
#pragma unroll
        for (int k = 0; k < 7; k++) l[k] = lp[k];
        float m = l[0];
#pragma unroll
        for (int k = 1; k < 7; k++) m = fmaxf(m, l[k]);
        am[e] = m;
#pragma unroll
        for (int k = 0; k < 7; k++) Pk[e][k] = __expf(l[k] - m);  // invalid -> 0
    }

    // l = 0: score0 = emis[0,b,:] + prior
    float4 emv = *(const float4*)(g_emis + (size_t)b * SS + j0);
    float4 prv = *(const float4*)(g_prior + j0);
    float sc[4];
    sc[0] = emv.x + prv.x; sc[1] = emv.y + prv.y;
    sc[2] = emv.z + prv.z; sc[3] = emv.w + prv.w;
    *(float4*)(out + (size_t)b * SS + j0) = make_float4(sc[0], sc[1], sc[2], sc[3]);

    // block max of scores (REDUX two-level)
    float lm = fmaxf(fmaxf(sc[0], sc[1]), fmaxf(sc[2], sc[3]));
    unsigned km = __reduce_max_sync(0xffffffffu, f2key(lm));
    if (lane == 0) wkey[wid] = km;

    // prefetch emission for l = 1
    float4 emn = *(const float4*)(g_emis + (size_t)(BB + b) * SS + j0);

    __syncthreads();
    float smax = key2f(__reduce_max_sync(0xffffffffu, wkey[lane]));

    for (int l = 1; l < LL; l++) {
        // stage p = exp(score - smax)
        float4 p;
        p.x = __expf(sc[0] - smax); p.y = __expf(sc[1] - smax);
        p.z = __expf(sc[2] - smax); p.w = __expf(sc[3] - smax);
        *(float4*)(pbuf + j0) = p;

        // emission + amax add-back (off the critical path)
        float emr[4] = {emn.x + am[0], emn.y + am[1], emn.z + am[2], emn.w + am[3]};
        // prefetch next step's emission
        if (l + 1 < LL)
            emn = *(const float4*)(g_emis + (size_t)((l + 1) * BB + b) * SS + j0);

        __syncthreads();   // [A] pbuf published

        // gathers (clamped neighbors fall back to self; Pk==0 kills invalid)
        float cm1 = (x0 > 0)  ? pbuf[j0 - 1] : p.x;
        float cp4 = (x0 < 12) ? pbuf[j0 + 4] : p.w;
        float4 yp = (y < 15) ? *(const float4*)(pbuf + j0 + 16)  : p;
        float4 ym = (y > 0)  ? *(const float4*)(pbuf + j0 - 16)  : p;
        float4 zp = (z < 15) ? *(const float4*)(pbuf + j0 + 256) : p;
        float4 zq = (z < 14) ? *(const float4*)(pbuf + j0 + 512) : p;

        float pc[4]  = {p.x, p.y, p.z, p.w};
        float pxp[4] = {p.y, p.z, p.w, cp4};
        float pxm[4] = {cm1, p.x, p.y, p.z};
        float pyp[4] = {yp.x, yp.y, yp.z, yp.w};
        float pym[4] = {ym.x, ym.y, ym.z, ym.w};
        float pzp[4] = {zp.x, zp.y, zp.z, zp.w};
        float pzq[4] = {zq.x, zq.y, zq.z, zq.w};

        float lmn = -1e30f;
#pragma unroll
        for (int e = 0; e < 4; e++) {
            float q = pc[e]  * Pk[e][0];
            q = fmaf(pxp[e], Pk[e][1], q);
            q = fmaf(pxm[e], Pk[e][2], q);
            q = fmaf(pyp[e], Pk[e][3], q);
            q = fmaf(pym[e], Pk[e][4], q);
            q = fmaf(pzp[e], Pk[e][5], q);
            q = fmaf(pzq[e], Pk[e][6], q);
            sc[e] = emr[e] + __logf(q) + smax;
            lmn = fmaxf(lmn, sc[e]);
        }
        *(float4*)(out + (size_t)(l * BB + b) * SS + j0) =
            make_float4(sc[0], sc[1], sc[2], sc[3]);

        // block max for next step's normalizer
        km = __reduce_max_sync(0xffffffffu, f2key(lmn));
        if (lane == 0) wkey[wid] = km;
        __syncthreads();   // [B] wkey published; also guards pbuf WAR
        smax = key2f(__reduce_max_sync(0xffffffffu, wkey[lane]));
    }
}

// ---------------------------------------------------------------------------
extern "C" void kernel_launch(void* const* d_in, const int* in_sizes, int n_in,
                              void* d_out, int out_size) {
    const int*   stories = nullptr;
    const float* trans_w = nullptr;
    const float* emis_w  = nullptr;
    const float* prior_w = nullptr;
    for (int i = 0; i < n_in; i++) {
        switch (in_sizes[i]) {
            case 2048:            stories = (const int*)d_in[i];   break;
            case 28672:           trans_w = (const float*)d_in[i]; break;
            case SS * VV:         emis_w  = (const float*)d_in[i]; break;
            case SS:              prior_w = (const float*)d_in[i]; break;
            default: break;
        }
    }
    float* out = (float*)d_out;

    const int smt_smem = 256 * 67 * sizeof(float);   // 68608 B
    cudaFuncSetAttribute(k_smt, cudaFuncAttributeMaxDynamicSharedMemorySize, smt_smem);

    k_row_lse<<<512, 256>>>(emis_w);
    k_small<<<5, 1024>>>(prior_w, trans_w);
    k_smt<<<dim3(VV / 64, ZP), 512, smt_smem>>>(emis_w);
    k_emis<<<dim3(SS / 256, LL * BB), 256>>>(stories);
    k_fwd<<<BB, 1024>>>(out);
    (void)out_size;
}